// round 7
// baseline (speedup 1.0000x reference)
#include <cuda_runtime.h>
#include <mma.h>

using namespace nvcuda;

#define NN     50000
#define F0     128
#define HC     256
#define NHEADS 4
#define CH     64
#define EMAX   900000
#define SLOPE  0.2f

// ---------------- scratch (static device globals; no allocs allowed) -------
__device__ float g_h[(long long)NN * HC];   // post-GEMM features, current layer
__device__ float g_x[(long long)NN * HC];   // layer output / next layer input
__device__ float g_as[NN * NHEADS];         // a_src per node/head
__device__ float g_ad[NN * NHEADS];         // a_dst per node/head
__device__ int   g_rowptr[NN + 1];          // CSR by destination
__device__ int   g_off[NN];                 // counts / running offsets
__device__ int   g_col[EMAX];               // src node per CSR slot

// ---------------- CSR build ------------------------------------------------
__global__ void zero_off_kernel() {
    int i = blockIdx.x * blockDim.x + threadIdx.x;
    if (i < NN) g_off[i] = 0;
}

__global__ void count_kernel(const int* __restrict__ dst, int E) {
    int e = blockIdx.x * blockDim.x + threadIdx.x;
    if (e < E) atomicAdd(&g_off[dst[e]], 1);
}

__global__ void scan_kernel() {
    __shared__ int part[1024];
    int t = threadIdx.x;
    const int CHK = (NN + 1023) / 1024;
    int lo = t * CHK;
    int hi = lo + CHK; if (hi > NN) hi = NN;
    if (lo > NN) lo = NN;
    int s = 0;
    for (int i = lo; i < hi; i++) s += g_off[i];
    part[t] = s;
    __syncthreads();
    for (int d = 1; d < 1024; d <<= 1) {
        int v = (t >= d) ? part[t - d] : 0;
        __syncthreads();
        part[t] += v;
        __syncthreads();
    }
    int pre = (t == 0) ? 0 : part[t - 1];
    for (int i = lo; i < hi; i++) {
        int c = g_off[i];
        g_rowptr[i] = pre;
        g_off[i]    = pre;
        pre += c;
    }
    if (t == 1023) g_rowptr[NN] = part[1023];
}

__global__ void scatter_kernel(const int* __restrict__ src,
                               const int* __restrict__ dst, int E) {
    int e = blockIdx.x * blockDim.x + threadIdx.x;
    if (e < E) {
        int p = atomicAdd(&g_off[dst[e]], 1);
        g_col[p] = src[e];
    }
}

// ---------------- TF32 tensor-core GEMM via wmma (round-4 version) ---------
// BM=128, BN=64, BK=32. 256 threads = 8 warps (4m x 2n), warp tile 32x32 =
// 2x2 wmma m16n16k8 tf32 fragments. cvt to tf32 once at smem store.

#define BM 128
#define BN 64
#define BK 32
#define APAD 4
#define BPAD 4

__global__ __launch_bounds__(256)
void gemm_tf32_kernel(const float* __restrict__ A,
                      const float* __restrict__ B,
                      float* __restrict__ Cmat, int M, int K) {
    __shared__ float As[BM][BK + APAD];   // [m][k] (tf32 bits in float)
    __shared__ float Bs[BK][BN + BPAD];   // [k][n]

    int tid  = threadIdx.x;
    int warp = tid >> 5;
    int wm   = warp >> 1;        // 0..3 -> m offset wm*32
    int wn   = warp & 1;         // 0..1 -> n offset wn*32

    int m0 = blockIdx.y * BM;
    int n0 = blockIdx.x * BN;

    int ar = tid >> 1;
    int ak = (tid & 1) * 16;
    int br = tid >> 3;
    int bc = (tid & 7) * 8;

    wmma::fragment<wmma::accumulator, 16, 16, 8, float> c[2][2];
#pragma unroll
    for (int i = 0; i < 2; i++)
#pragma unroll
        for (int j = 0; j < 2; j++)
            wmma::fill_fragment(c[i][j], 0.0f);

    for (int k0 = 0; k0 < K; k0 += BK) {
        bool arow_ok = (m0 + ar) < M;
        const float* ap = A + (long long)(m0 + ar) * K + k0 + ak;
#pragma unroll
        for (int i = 0; i < 4; i++) {
            float4 v = arow_ok ? *(const float4*)(ap + i * 4)
                               : make_float4(0.f, 0.f, 0.f, 0.f);
            As[ar][ak + i * 4 + 0] = wmma::__float_to_tf32(v.x);
            As[ar][ak + i * 4 + 1] = wmma::__float_to_tf32(v.y);
            As[ar][ak + i * 4 + 2] = wmma::__float_to_tf32(v.z);
            As[ar][ak + i * 4 + 3] = wmma::__float_to_tf32(v.w);
        }
        const float* bp = B + (long long)(k0 + br) * HC + n0 + bc;
#pragma unroll
        for (int i = 0; i < 2; i++) {
            float4 v = *(const float4*)(bp + i * 4);
            Bs[br][bc + i * 4 + 0] = wmma::__float_to_tf32(v.x);
            Bs[br][bc + i * 4 + 1] = wmma::__float_to_tf32(v.y);
            Bs[br][bc + i * 4 + 2] = wmma::__float_to_tf32(v.z);
            Bs[br][bc + i * 4 + 3] = wmma::__float_to_tf32(v.w);
        }
        __syncthreads();

#pragma unroll
        for (int kk = 0; kk < BK; kk += 8) {
            wmma::fragment<wmma::matrix_a, 16, 16, 8,
                           wmma::precision::tf32, wmma::row_major> a[2];
            wmma::fragment<wmma::matrix_b, 16, 16, 8,
                           wmma::precision::tf32, wmma::row_major> b[2];
#pragma unroll
            for (int i = 0; i < 2; i++)
                wmma::load_matrix_sync(a[i], &As[wm * 32 + i * 16][kk], BK + APAD);
#pragma unroll
            for (int j = 0; j < 2; j++)
                wmma::load_matrix_sync(b[j], &Bs[kk][wn * 32 + j * 16], BN + BPAD);
#pragma unroll
            for (int i = 0; i < 2; i++)
#pragma unroll
                for (int j = 0; j < 2; j++)
                    wmma::mma_sync(c[i][j], a[i], b[j], c[i][j]);
        }
        __syncthreads();
    }

#pragma unroll
    for (int i = 0; i < 2; i++) {
        int row0 = m0 + wm * 32 + i * 16;
        if (row0 >= M) continue;
#pragma unroll
        for (int j = 0; j < 2; j++) {
            int col0 = n0 + wn * 32 + j * 16;
            wmma::store_matrix_sync(&Cmat[(long long)row0 * HC + col0],
                                    c[i][j], HC, wmma::mem_row_major);
        }
    }
}

// ---------------- attention logits: a_src/a_dst per (node, head) -----------
__global__ void attn_kernel(const float* __restrict__ att_src,
                            const float* __restrict__ att_dst) {
    int gw = (blockIdx.x * blockDim.x + threadIdx.x) >> 5;
    int lane = threadIdx.x & 31;
    if (gw >= NN * NHEADS) return;
    int n = gw >> 2, hd = gw & 3;
    const float* hp = &g_h[(long long)n * HC + hd * CH];
    float h0 = hp[lane], h1 = hp[lane + 32];
    float s1 = h0 * att_src[hd * CH + lane] + h1 * att_src[hd * CH + lane + 32];
    float s2 = h0 * att_dst[hd * CH + lane] + h1 * att_dst[hd * CH + lane + 32];
#pragma unroll
    for (int d = 16; d; d >>= 1) {
        s1 += __shfl_xor_sync(0xffffffffu, s1, d);
        s2 += __shfl_xor_sync(0xffffffffu, s2, d);
    }
    if (lane == 0) {
        g_as[n * NHEADS + hd] = s1;
        g_ad[n * NHEADS + hd] = s2;
    }
}

// ---------------- aggregation v2: warp/node, chunked two-phase pass 2 ------
// Pass 1: warp-parallel max of leaky(a_src[s]+a_dst[n]) per head (as before).
// Pass 2: per 32-edge chunk, phase A computes ex for all 4 heads lane-parallel
// into per-warp smem (32 independent g_as gathers in flight); phase B streams
// the 1KB h-gathers with only LDS-broadcast scalars on the dependent path.
__global__ void agg_kernel(const float* __restrict__ bias, float* __restrict__ out) {
    __shared__ float s_ex[8][32][4];
    __shared__ int   s_col[8][32];
    int wip  = threadIdx.x >> 5;
    int warp = blockIdx.x * 8 + wip;
    int lane = threadIdx.x & 31;
    if (warp >= NN) return;
    int n = warp;
    int beg = g_rowptr[n], end = g_rowptr[n + 1];
    float4 ad4 = *(const float4*)&g_ad[n * 4];

    // pass 1: per-head max
    float m0 = -1e30f, m1 = -1e30f, m2 = -1e30f, m3 = -1e30f;
    for (int e = beg + lane; e < end; e += 32) {
        int s = g_col[e];
        float4 a4 = *(const float4*)&g_as[s * 4];
        float v;
        v = a4.x + ad4.x; v = v > 0.f ? v : SLOPE * v; m0 = fmaxf(m0, v);
        v = a4.y + ad4.y; v = v > 0.f ? v : SLOPE * v; m1 = fmaxf(m1, v);
        v = a4.z + ad4.z; v = v > 0.f ? v : SLOPE * v; m2 = fmaxf(m2, v);
        v = a4.w + ad4.w; v = v > 0.f ? v : SLOPE * v; m3 = fmaxf(m3, v);
    }
#pragma unroll
    for (int d = 16; d; d >>= 1) {
        m0 = fmaxf(m0, __shfl_xor_sync(0xffffffffu, m0, d));
        m1 = fmaxf(m1, __shfl_xor_sync(0xffffffffu, m1, d));
        m2 = fmaxf(m2, __shfl_xor_sync(0xffffffffu, m2, d));
        m3 = fmaxf(m3, __shfl_xor_sync(0xffffffffu, m3, d));
    }

    int hd = lane >> 3;
    int cbase = lane * 8;
    float acc[8] = {0.f, 0.f, 0.f, 0.f, 0.f, 0.f, 0.f, 0.f};
    float den = 0.f;

    for (int base = beg; base < end; base += 32) {
        // phase A: lane-parallel ex computation into per-warp smem
        int e = base + lane;
        if (e < end) {
            int s = g_col[e];
            float4 a4 = *(const float4*)&g_as[s * 4];
            float v;
            v = a4.x + ad4.x; v = v > 0.f ? v : SLOPE * v;
            s_ex[wip][lane][0] = __expf(v - m0);
            v = a4.y + ad4.y; v = v > 0.f ? v : SLOPE * v;
            s_ex[wip][lane][1] = __expf(v - m1);
            v = a4.z + ad4.z; v = v > 0.f ? v : SLOPE * v;
            s_ex[wip][lane][2] = __expf(v - m2);
            v = a4.w + ad4.w; v = v > 0.f ? v : SLOPE * v;
            s_ex[wip][lane][3] = __expf(v - m3);
            s_col[wip][lane] = s;
        }
        __syncwarp();
        // phase B: stream h-gathers, independent loads
        int cnt = end - base; if (cnt > 32) cnt = 32;
        for (int i = 0; i < cnt; i++) {
            int   sc = s_col[wip][i];
            float ex = s_ex[wip][i][hd];
            den += ex;
            const float4* hp = (const float4*)&g_h[(long long)sc * HC + cbase];
            float4 h0 = hp[0], h1 = hp[1];
            acc[0] += ex * h0.x; acc[1] += ex * h0.y;
            acc[2] += ex * h0.z; acc[3] += ex * h0.w;
            acc[4] += ex * h1.x; acc[5] += ex * h1.y;
            acc[6] += ex * h1.z; acc[7] += ex * h1.w;
        }
        __syncwarp();
    }

    float inv = 1.f / (den + 1e-16f);
    float4 b0 = *(const float4*)&bias[cbase];
    float4 b1 = *(const float4*)&bias[cbase + 4];
    float4 o0, o1;
    o0.x = fmaxf(acc[0] * inv + b0.x, 0.f);
    o0.y = fmaxf(acc[1] * inv + b0.y, 0.f);
    o0.z = fmaxf(acc[2] * inv + b0.z, 0.f);
    o0.w = fmaxf(acc[3] * inv + b0.w, 0.f);
    o1.x = fmaxf(acc[4] * inv + b1.x, 0.f);
    o1.y = fmaxf(acc[5] * inv + b1.y, 0.f);
    o1.z = fmaxf(acc[6] * inv + b1.z, 0.f);
    o1.w = fmaxf(acc[7] * inv + b1.w, 0.f);
    *(float4*)&out[(long long)n * HC + cbase]     = o0;
    *(float4*)&out[(long long)n * HC + cbase + 4] = o1;
}

// ---------------- launcher -------------------------------------------------
extern "C" void kernel_launch(void* const* d_in, const int* in_sizes, int n_in,
                              void* d_out, int out_size) {
    const float* x  = (const float*)d_in[0];
    const int*   ei = (const int*)d_in[1];
    int E = in_sizes[1] / 2;
    const int* src = ei;
    const int* dst = ei + E;

    const float* W[3]  = {(const float*)d_in[2], (const float*)d_in[6],  (const float*)d_in[10]};
    const float* AS[3] = {(const float*)d_in[3], (const float*)d_in[7],  (const float*)d_in[11]};
    const float* AD[3] = {(const float*)d_in[4], (const float*)d_in[8],  (const float*)d_in[12]};
    const float* BI[3] = {(const float*)d_in[5], (const float*)d_in[9],  (const float*)d_in[13]};
    float* out = (float*)d_out;

    float* gx = nullptr;
    float* gh = nullptr;
    cudaGetSymbolAddress((void**)&gx, g_x);
    cudaGetSymbolAddress((void**)&gh, g_h);

    // CSR build (edge_index is identical for all layers)
    zero_off_kernel<<<(NN + 255) / 256, 256>>>();
    count_kernel<<<(E + 255) / 256, 256>>>(dst, E);
    scan_kernel<<<1, 1024>>>();
    scatter_kernel<<<(E + 255) / 256, 256>>>(src, dst, E);

    dim3 ggrid(HC / BN, (NN + BM - 1) / BM);
    int attn_blocks = (NN * NHEADS * 32 + 255) / 256;
    int agg_blocks  = (NN + 7) / 8;

    // layer 0 (K = 128)
    gemm_tf32_kernel<<<ggrid, 256>>>(x, W[0], gh, NN, F0);
    attn_kernel<<<attn_blocks, 256>>>(AS[0], AD[0]);
    agg_kernel<<<agg_blocks, 256>>>(BI[0], gx);

    // layer 1 (K = 256)
    gemm_tf32_kernel<<<ggrid, 256>>>(gx, W[1], gh, NN, HC);
    attn_kernel<<<attn_blocks, 256>>>(AS[1], AD[1]);
    agg_kernel<<<agg_blocks, 256>>>(BI[1], gx);

    // layer 2 (K = 256), write final output
    gemm_tf32_kernel<<<ggrid, 256>>>(gx, W[2], gh, NN, HC);
    attn_kernel<<<attn_blocks, 256>>>(AS[2], AD[2]);
    agg_kernel<<<agg_blocks, 256>>>(BI[2], out);
}

// round 11
// speedup vs baseline: 1.1291x; 1.1291x over previous
#include <cuda_runtime.h>
#include <cuda_pipeline.h>
#include <mma.h>

using namespace nvcuda;

#define NN     50000
#define F0     128
#define HC     256
#define NHEADS 4
#define CH     64
#define EMAX   900000
#define SLOPE  0.2f

// ---------------- scratch (static device globals; no allocs allowed) -------
__device__ float g_h[(long long)NN * HC];   // post-GEMM features, current layer
__device__ float g_x[(long long)NN * HC];   // layer output / next layer input
__device__ float g_as[NN * NHEADS];         // a_src per node/head
__device__ float g_ad[NN * NHEADS];         // a_dst per node/head
__device__ int   g_rowptr[NN + 1];          // CSR by destination
__device__ int   g_off[NN];                 // counts / running offsets
__device__ int   g_col[EMAX];               // src node per CSR slot

// ---------------- CSR build ------------------------------------------------
__global__ void zero_off_kernel() {
    int i = blockIdx.x * blockDim.x + threadIdx.x;
    if (i < NN) g_off[i] = 0;
}

__global__ void count_kernel(const int* __restrict__ dst, int E) {
    int e = blockIdx.x * blockDim.x + threadIdx.x;
    if (e < E) atomicAdd(&g_off[dst[e]], 1);
}

__global__ void scan_kernel() {
    __shared__ int part[1024];
    int t = threadIdx.x;
    const int CHK = (NN + 1023) / 1024;
    int lo = t * CHK;
    int hi = lo + CHK; if (hi > NN) hi = NN;
    if (lo > NN) lo = NN;
    int s = 0;
    for (int i = lo; i < hi; i++) s += g_off[i];
    part[t] = s;
    __syncthreads();
    for (int d = 1; d < 1024; d <<= 1) {
        int v = (t >= d) ? part[t - d] : 0;
        __syncthreads();
        part[t] += v;
        __syncthreads();
    }
    int pre = (t == 0) ? 0 : part[t - 1];
    for (int i = lo; i < hi; i++) {
        int c = g_off[i];
        g_rowptr[i] = pre;
        g_off[i]    = pre;
        pre += c;
    }
    if (t == 1023) g_rowptr[NN] = part[1023];
}

__global__ void scatter_kernel(const int* __restrict__ src,
                               const int* __restrict__ dst, int E) {
    int e = blockIdx.x * blockDim.x + threadIdx.x;
    if (e < E) {
        int p = atomicAdd(&g_off[dst[e]], 1);
        g_col[p] = src[e];
    }
}

// ---------------- TF32 GEMM v4: C = A[M,K] @ B[K,256] ----------------------
// BM=128, BN=256 (full width), BK=16. 8 warps in 2(m) x 4(n); warp tile
// 64x64 = 4x4 wmma m16n16k8 fragments. cp.async double-buffered (raw fp32);
// RN rounding to tf32 applied in-fragment (cvt.rna) — required for accuracy.

#define BM 128
#define BN 256
#define BK 16
#define A_LD 20                    // BK + 4 pad
#define B_LD 264                   // BN + 8 pad (keeps 16B alignment)
#define A_TILE (BM * A_LD)         // 2560 floats
#define B_TILE (BK * B_LD)         // 4224 floats
#define GEMM_SMEM_BYTES ((2 * A_TILE + 2 * B_TILE) * 4)   // 54272 B

__global__ __launch_bounds__(256, 1)
void gemm_tf32_kernel(const float* __restrict__ A,
                      const float* __restrict__ B,
                      float* __restrict__ Cmat, int M, int K) {
    extern __shared__ float smem[];
    float* Asm = smem;                 // [2][BM][A_LD]
    float* Bsm = smem + 2 * A_TILE;    // [2][BK][B_LD]

    int tid  = threadIdx.x;
    int warp = tid >> 5;
    int wm   = warp >> 2;        // 0..1 -> m offset wm*64
    int wn   = warp & 3;         // 0..3 -> n offset wn*64

    int m0 = blockIdx.x * BM;

    wmma::fragment<wmma::accumulator, 16, 16, 8, float> acc[4][4];
#pragma unroll
    for (int i = 0; i < 4; i++)
#pragma unroll
        for (int j = 0; j < 4; j++)
            wmma::fill_fragment(acc[i][j], 0.0f);

    const int nk = K / BK;

    // ---- async tile loaders (raw fp32, 16B chunks) ----
    auto load_tiles = [&](int it, int buf) {
        int k0 = it * BK;
        // A: 128 x 16 = 512 float4, 2 per thread
#pragma unroll
        for (int i = 0; i < 2; i++) {
            int idx = tid + i * 256;           // 0..511
            int r   = idx >> 2;
            int c4  = (idx & 3) * 4;
            int row = m0 + r; if (row >= M) row = M - 1;   // clamp; store guarded
            __pipeline_memcpy_async(Asm + buf * A_TILE + r * A_LD + c4,
                                    A + (long long)row * K + k0 + c4, 16);
        }
        // B: 16 x 256 = 1024 float4, 4 per thread
#pragma unroll
        for (int i = 0; i < 4; i++) {
            int idx = tid + i * 256;           // 0..1023
            int r   = idx >> 6;
            int c4  = (idx & 63) * 4;
            __pipeline_memcpy_async(Bsm + buf * B_TILE + r * B_LD + c4,
                                    B + (long long)(k0 + r) * HC + c4, 16);
        }
        __pipeline_commit();
    };

    load_tiles(0, 0);

    int buf = 0;
    for (int it = 0; it < nk; it++) {
        __pipeline_wait_prior(0);
        __syncthreads();

        if (it + 1 < nk) load_tiles(it + 1, buf ^ 1);

        const float* Ab = Asm + buf * A_TILE;
        const float* Bb = Bsm + buf * B_TILE;
#pragma unroll
        for (int kk = 0; kk < BK; kk += 8) {
            wmma::fragment<wmma::matrix_a, 16, 16, 8,
                           wmma::precision::tf32, wmma::row_major> a[4];
            wmma::fragment<wmma::matrix_b, 16, 16, 8,
                           wmma::precision::tf32, wmma::row_major> b[4];
#pragma unroll
            for (int i = 0; i < 4; i++) {
                wmma::load_matrix_sync(a[i], Ab + (wm * 64 + i * 16) * A_LD + kk, A_LD);
#pragma unroll
                for (int t = 0; t < a[i].num_elements; t++)
                    a[i].x[t] = wmma::__float_to_tf32(a[i].x[t]);
            }
#pragma unroll
            for (int j = 0; j < 4; j++) {
                wmma::load_matrix_sync(b[j], Bb + kk * B_LD + wn * 64 + j * 16, B_LD);
#pragma unroll
                for (int t = 0; t < b[j].num_elements; t++)
                    b[j].x[t] = wmma::__float_to_tf32(b[j].x[t]);
            }
#pragma unroll
            for (int i = 0; i < 4; i++)
#pragma unroll
                for (int j = 0; j < 4; j++)
                    wmma::mma_sync(acc[i][j], a[i], b[j], acc[i][j]);
        }
        buf ^= 1;
    }

    // epilogue: per-fragment row guard (M % 16 == 0 makes this exact)
#pragma unroll
    for (int i = 0; i < 4; i++) {
        int row0 = m0 + wm * 64 + i * 16;
        if (row0 >= M) continue;
#pragma unroll
        for (int j = 0; j < 4; j++) {
            int col0 = wn * 64 + j * 16;
            wmma::store_matrix_sync(&Cmat[(long long)row0 * HC + col0],
                                    acc[i][j], HC, wmma::mem_row_major);
        }
    }
}

// ---------------- attention logits: a_src/a_dst per (node, head) -----------
__global__ void attn_kernel(const float* __restrict__ att_src,
                            const float* __restrict__ att_dst) {
    int gw = (blockIdx.x * blockDim.x + threadIdx.x) >> 5;
    int lane = threadIdx.x & 31;
    if (gw >= NN * NHEADS) return;
    int n = gw >> 2, hd = gw & 3;
    const float* hp = &g_h[(long long)n * HC + hd * CH];
    float h0 = hp[lane], h1 = hp[lane + 32];
    float s1 = h0 * att_src[hd * CH + lane] + h1 * att_src[hd * CH + lane + 32];
    float s2 = h0 * att_dst[hd * CH + lane] + h1 * att_dst[hd * CH + lane + 32];
#pragma unroll
    for (int d = 16; d; d >>= 1) {
        s1 += __shfl_xor_sync(0xffffffffu, s1, d);
        s2 += __shfl_xor_sync(0xffffffffu, s2, d);
    }
    if (lane == 0) {
        g_as[n * NHEADS + hd] = s1;
        g_ad[n * NHEADS + hd] = s2;
    }
}

// ---------------- aggregation: warp per destination node (round-4 ver) -----
__global__ void agg_kernel(const float* __restrict__ bias, float* __restrict__ out) {
    int warp = (blockIdx.x * blockDim.x + threadIdx.x) >> 5;
    int lane = threadIdx.x & 31;
    if (warp >= NN) return;
    int n = warp;
    int beg = g_rowptr[n], end = g_rowptr[n + 1];
    float4 ad4 = *(const float4*)&g_ad[n * 4];

    float m0 = -1e30f, m1 = -1e30f, m2 = -1e30f, m3 = -1e30f;
    for (int e = beg + lane; e < end; e += 32) {
        int s = g_col[e];
        float4 a4 = *(const float4*)&g_as[s * 4];
        float v;
        v = a4.x + ad4.x; v = v > 0.f ? v : SLOPE * v; m0 = fmaxf(m0, v);
        v = a4.y + ad4.y; v = v > 0.f ? v : SLOPE * v; m1 = fmaxf(m1, v);
        v = a4.z + ad4.z; v = v > 0.f ? v : SLOPE * v; m2 = fmaxf(m2, v);
        v = a4.w + ad4.w; v = v > 0.f ? v : SLOPE * v; m3 = fmaxf(m3, v);
    }
#pragma unroll
    for (int d = 16; d; d >>= 1) {
        m0 = fmaxf(m0, __shfl_xor_sync(0xffffffffu, m0, d));
        m1 = fmaxf(m1, __shfl_xor_sync(0xffffffffu, m1, d));
        m2 = fmaxf(m2, __shfl_xor_sync(0xffffffffu, m2, d));
        m3 = fmaxf(m3, __shfl_xor_sync(0xffffffffu, m3, d));
    }
    int hd = lane >> 3;
    float mh  = (hd == 0) ? m0 : (hd == 1) ? m1 : (hd == 2) ? m2 : m3;
    float adh = (hd == 0) ? ad4.x : (hd == 1) ? ad4.y : (hd == 2) ? ad4.z : ad4.w;

    int cbase = lane * 8;
    float acc[8] = {0.f, 0.f, 0.f, 0.f, 0.f, 0.f, 0.f, 0.f};
    float den = 0.f;
    for (int e = beg; e < end; e++) {
        int s = g_col[e];
        float av = g_as[s * 4 + hd];
        float ee = av + adh;
        ee = ee > 0.f ? ee : SLOPE * ee;
        float ex = __expf(ee - mh);
        den += ex;
        const float4* hp = (const float4*)&g_h[(long long)s * HC + cbase];
        float4 h0 = hp[0], h1 = hp[1];
        acc[0] += ex * h0.x; acc[1] += ex * h0.y; acc[2] += ex * h0.z; acc[3] += ex * h0.w;
        acc[4] += ex * h1.x; acc[5] += ex * h1.y; acc[6] += ex * h1.z; acc[7] += ex * h1.w;
    }
    float inv = 1.f / (den + 1e-16f);
    float4 b0 = *(const float4*)&bias[cbase];
    float4 b1 = *(const float4*)&bias[cbase + 4];
    float4 o0, o1;
    o0.x = fmaxf(acc[0] * inv + b0.x, 0.f);
    o0.y = fmaxf(acc[1] * inv + b0.y, 0.f);
    o0.z = fmaxf(acc[2] * inv + b0.z, 0.f);
    o0.w = fmaxf(acc[3] * inv + b0.w, 0.f);
    o1.x = fmaxf(acc[4] * inv + b1.x, 0.f);
    o1.y = fmaxf(acc[5] * inv + b1.y, 0.f);
    o1.z = fmaxf(acc[6] * inv + b1.z, 0.f);
    o1.w = fmaxf(acc[7] * inv + b1.w, 0.f);
    *(float4*)&out[(long long)n * HC + cbase]     = o0;
    *(float4*)&out[(long long)n * HC + cbase + 4] = o1;
}

// ---------------- launcher -------------------------------------------------
extern "C" void kernel_launch(void* const* d_in, const int* in_sizes, int n_in,
                              void* d_out, int out_size) {
    const float* x  = (const float*)d_in[0];
    const int*   ei = (const int*)d_in[1];
    int E = in_sizes[1] / 2;
    const int* src = ei;
    const int* dst = ei + E;

    const float* W[3]  = {(const float*)d_in[2], (const float*)d_in[6],  (const float*)d_in[10]};
    const float* AS[3] = {(const float*)d_in[3], (const float*)d_in[7],  (const float*)d_in[11]};
    const float* AD[3] = {(const float*)d_in[4], (const float*)d_in[8],  (const float*)d_in[12]};
    const float* BI[3] = {(const float*)d_in[5], (const float*)d_in[9],  (const float*)d_in[13]};
    float* out = (float*)d_out;

    float* gx = nullptr;
    float* gh = nullptr;
    cudaGetSymbolAddress((void**)&gx, g_x);
    cudaGetSymbolAddress((void**)&gh, g_h);

    cudaFuncSetAttribute(gemm_tf32_kernel,
                         cudaFuncAttributeMaxDynamicSharedMemorySize,
                         GEMM_SMEM_BYTES);

    // CSR build (edge_index is identical for all layers)
    zero_off_kernel<<<(NN + 255) / 256, 256>>>();
    count_kernel<<<(E + 255) / 256, 256>>>(dst, E);
    scan_kernel<<<1, 1024>>>();
    scatter_kernel<<<(E + 255) / 256, 256>>>(src, dst, E);

    int ggrid = (NN + BM - 1) / BM;   // 391 blocks, BN covers full HC
    int attn_blocks = (NN * NHEADS * 32 + 255) / 256;
    int agg_blocks  = (NN + 7) / 8;

    // layer 0 (K = 128)
    gemm_tf32_kernel<<<ggrid, 256, GEMM_SMEM_BYTES>>>(x, W[0], gh, NN, F0);
    attn_kernel<<<attn_blocks, 256>>>(AS[0], AD[0]);
    agg_kernel<<<agg_blocks, 256>>>(BI[0], gx);

    // layer 1 (K = 256)
    gemm_tf32_kernel<<<ggrid, 256, GEMM_SMEM_BYTES>>>(gx, W[1], gh, NN, HC);
    attn_kernel<<<attn_blocks, 256>>>(AS[1], AD[1]);
    agg_kernel<<<agg_blocks, 256>>>(BI[1], gx);

    // layer 2 (K = 256), write final output
    gemm_tf32_kernel<<<ggrid, 256, GEMM_SMEM_BYTES>>>(gx, W[2], gh, NN, HC);
    attn_kernel<<<attn_blocks, 256>>>(AS[2], AD[2]);
    agg_kernel<<<agg_blocks, 256>>>(BI[2], out);
}

// round 12
// speedup vs baseline: 1.2514x; 1.1083x over previous
#include <cuda_runtime.h>
#include <cuda_pipeline.h>
#include <cuda_bf16.h>
#include <mma.h>

using namespace nvcuda;

#define NN     50000
#define F0     128
#define HC     256
#define NHEADS 4
#define CH     64
#define EMAX   900000
#define SLOPE  0.2f

// ---------------- scratch (static device globals; no allocs allowed) -------
__device__ float g_h[(long long)NN * HC];   // post-GEMM features, current layer
__device__ __nv_bfloat16 g_hb[(long long)NN * HC];  // bf16 copy for gathers
__device__ float g_x[(long long)NN * HC];   // layer output / next layer input
__device__ float g_as[NN * NHEADS];         // a_src per node/head
__device__ float g_ad[NN * NHEADS];         // a_dst per node/head
__device__ int   g_rowptr[NN + 1];          // CSR by destination
__device__ int   g_off[NN];                 // counts / running offsets
__device__ int   g_col[EMAX];               // src node per CSR slot

// ---------------- CSR build ------------------------------------------------
__global__ void zero_off_kernel() {
    int i = blockIdx.x * blockDim.x + threadIdx.x;
    if (i < NN) g_off[i] = 0;
}

__global__ void count_kernel(const int* __restrict__ dst, int E) {
    int e = blockIdx.x * blockDim.x + threadIdx.x;
    if (e < E) atomicAdd(&g_off[dst[e]], 1);
}

__global__ void scan_kernel() {
    __shared__ int part[1024];
    int t = threadIdx.x;
    const int CHK = (NN + 1023) / 1024;
    int lo = t * CHK;
    int hi = lo + CHK; if (hi > NN) hi = NN;
    if (lo > NN) lo = NN;
    int s = 0;
    for (int i = lo; i < hi; i++) s += g_off[i];
    part[t] = s;
    __syncthreads();
    for (int d = 1; d < 1024; d <<= 1) {
        int v = (t >= d) ? part[t - d] : 0;
        __syncthreads();
        part[t] += v;
        __syncthreads();
    }
    int pre = (t == 0) ? 0 : part[t - 1];
    for (int i = lo; i < hi; i++) {
        int c = g_off[i];
        g_rowptr[i] = pre;
        g_off[i]    = pre;
        pre += c;
    }
    if (t == 1023) g_rowptr[NN] = part[1023];
}

__global__ void scatter_kernel(const int* __restrict__ src,
                               const int* __restrict__ dst, int E) {
    int e = blockIdx.x * blockDim.x + threadIdx.x;
    if (e < E) {
        int p = atomicAdd(&g_off[dst[e]], 1);
        g_col[p] = src[e];
    }
}

// ---------------- TF32 GEMM v4: C = A[M,K] @ B[K,256] ----------------------
// BM=128, BN=256 (full width), BK=16. 8 warps in 2(m) x 4(n); warp tile
// 64x64 = 4x4 wmma m16n16k8 fragments. cp.async double-buffered (raw fp32);
// RN rounding to tf32 applied in-fragment.

#define BM 128
#define BN 256
#define BK 16
#define A_LD 20
#define B_LD 264
#define A_TILE (BM * A_LD)
#define B_TILE (BK * B_LD)
#define GEMM_SMEM_BYTES ((2 * A_TILE + 2 * B_TILE) * 4)   // 54272 B

__global__ __launch_bounds__(256, 1)
void gemm_tf32_kernel(const float* __restrict__ A,
                      const float* __restrict__ B,
                      float* __restrict__ Cmat, int M, int K) {
    extern __shared__ float smem[];
    float* Asm = smem;                 // [2][BM][A_LD]
    float* Bsm = smem + 2 * A_TILE;    // [2][BK][B_LD]

    int tid  = threadIdx.x;
    int warp = tid >> 5;
    int wm   = warp >> 2;
    int wn   = warp & 3;

    int m0 = blockIdx.x * BM;

    wmma::fragment<wmma::accumulator, 16, 16, 8, float> acc[4][4];
#pragma unroll
    for (int i = 0; i < 4; i++)
#pragma unroll
        for (int j = 0; j < 4; j++)
            wmma::fill_fragment(acc[i][j], 0.0f);

    const int nk = K / BK;

    auto load_tiles = [&](int it, int buf) {
        int k0 = it * BK;
#pragma unroll
        for (int i = 0; i < 2; i++) {
            int idx = tid + i * 256;
            int r   = idx >> 2;
            int c4  = (idx & 3) * 4;
            int row = m0 + r; if (row >= M) row = M - 1;
            __pipeline_memcpy_async(Asm + buf * A_TILE + r * A_LD + c4,
                                    A + (long long)row * K + k0 + c4, 16);
        }
#pragma unroll
        for (int i = 0; i < 4; i++) {
            int idx = tid + i * 256;
            int r   = idx >> 6;
            int c4  = (idx & 63) * 4;
            __pipeline_memcpy_async(Bsm + buf * B_TILE + r * B_LD + c4,
                                    B + (long long)(k0 + r) * HC + c4, 16);
        }
        __pipeline_commit();
    };

    load_tiles(0, 0);

    int buf = 0;
    for (int it = 0; it < nk; it++) {
        __pipeline_wait_prior(0);
        __syncthreads();

        if (it + 1 < nk) load_tiles(it + 1, buf ^ 1);

        const float* Ab = Asm + buf * A_TILE;
        const float* Bb = Bsm + buf * B_TILE;
#pragma unroll
        for (int kk = 0; kk < BK; kk += 8) {
            wmma::fragment<wmma::matrix_a, 16, 16, 8,
                           wmma::precision::tf32, wmma::row_major> a[4];
            wmma::fragment<wmma::matrix_b, 16, 16, 8,
                           wmma::precision::tf32, wmma::row_major> b[4];
#pragma unroll
            for (int i = 0; i < 4; i++) {
                wmma::load_matrix_sync(a[i], Ab + (wm * 64 + i * 16) * A_LD + kk, A_LD);
#pragma unroll
                for (int t = 0; t < a[i].num_elements; t++)
                    a[i].x[t] = wmma::__float_to_tf32(a[i].x[t]);
            }
#pragma unroll
            for (int j = 0; j < 4; j++) {
                wmma::load_matrix_sync(b[j], Bb + kk * B_LD + wn * 64 + j * 16, B_LD);
#pragma unroll
                for (int t = 0; t < b[j].num_elements; t++)
                    b[j].x[t] = wmma::__float_to_tf32(b[j].x[t]);
            }
#pragma unroll
            for (int i = 0; i < 4; i++)
#pragma unroll
                for (int j = 0; j < 4; j++)
                    wmma::mma_sync(acc[i][j], a[i], b[j], acc[i][j]);
        }
        buf ^= 1;
    }

#pragma unroll
    for (int i = 0; i < 4; i++) {
        int row0 = m0 + wm * 64 + i * 16;
        if (row0 >= M) continue;
#pragma unroll
        for (int j = 0; j < 4; j++) {
            int col0 = wn * 64 + j * 16;
            wmma::store_matrix_sync(&Cmat[(long long)row0 * HC + col0],
                                    acc[i][j], HC, wmma::mem_row_major);
        }
    }
}

// ---------------- attention logits + bf16 copy of h ------------------------
// warp per (node, head): computes a_src/a_dst AND writes the bf16 copy of h
// (it already has the values in registers; adds only the bf16 stores).
__global__ void attn_kernel(const float* __restrict__ att_src,
                            const float* __restrict__ att_dst) {
    int gw = (blockIdx.x * blockDim.x + threadIdx.x) >> 5;
    int lane = threadIdx.x & 31;
    if (gw >= NN * NHEADS) return;
    int n = gw >> 2, hd = gw & 3;
    const float* hp = &g_h[(long long)n * HC + hd * CH];
    float h0 = hp[lane], h1 = hp[lane + 32];

    __nv_bfloat16* hbp = &g_hb[(long long)n * HC + hd * CH];
    hbp[lane]      = __float2bfloat16(h0);
    hbp[lane + 32] = __float2bfloat16(h1);

    float s1 = h0 * att_src[hd * CH + lane] + h1 * att_src[hd * CH + lane + 32];
    float s2 = h0 * att_dst[hd * CH + lane] + h1 * att_dst[hd * CH + lane + 32];
#pragma unroll
    for (int d = 16; d; d >>= 1) {
        s1 += __shfl_xor_sync(0xffffffffu, s1, d);
        s2 += __shfl_xor_sync(0xffffffffu, s2, d);
    }
    if (lane == 0) {
        g_as[n * NHEADS + hd] = s1;
        g_ad[n * NHEADS + hd] = s2;
    }
}

// ---------------- aggregation: warp/node, bf16 message gathers -------------
__global__ void agg_kernel(const float* __restrict__ bias, float* __restrict__ out) {
    int warp = (blockIdx.x * blockDim.x + threadIdx.x) >> 5;
    int lane = threadIdx.x & 31;
    if (warp >= NN) return;
    int n = warp;
    int beg = g_rowptr[n], end = g_rowptr[n + 1];
    float4 ad4 = *(const float4*)&g_ad[n * 4];

    float m0 = -1e30f, m1 = -1e30f, m2 = -1e30f, m3 = -1e30f;
    for (int e = beg + lane; e < end; e += 32) {
        int s = g_col[e];
        float4 a4 = *(const float4*)&g_as[s * 4];
        float v;
        v = a4.x + ad4.x; v = v > 0.f ? v : SLOPE * v; m0 = fmaxf(m0, v);
        v = a4.y + ad4.y; v = v > 0.f ? v : SLOPE * v; m1 = fmaxf(m1, v);
        v = a4.z + ad4.z; v = v > 0.f ? v : SLOPE * v; m2 = fmaxf(m2, v);
        v = a4.w + ad4.w; v = v > 0.f ? v : SLOPE * v; m3 = fmaxf(m3, v);
    }
#pragma unroll
    for (int d = 16; d; d >>= 1) {
        m0 = fmaxf(m0, __shfl_xor_sync(0xffffffffu, m0, d));
        m1 = fmaxf(m1, __shfl_xor_sync(0xffffffffu, m1, d));
        m2 = fmaxf(m2, __shfl_xor_sync(0xffffffffu, m2, d));
        m3 = fmaxf(m3, __shfl_xor_sync(0xffffffffu, m3, d));
    }
    int hd = lane >> 3;
    float mh  = (hd == 0) ? m0 : (hd == 1) ? m1 : (hd == 2) ? m2 : m3;
    float adh = (hd == 0) ? ad4.x : (hd == 1) ? ad4.y : (hd == 2) ? ad4.z : ad4.w;

    int cbase = lane * 8;
    float acc[8] = {0.f, 0.f, 0.f, 0.f, 0.f, 0.f, 0.f, 0.f};
    float den = 0.f;
    for (int e = beg; e < end; e++) {
        int s = g_col[e];
        float av = g_as[s * 4 + hd];
        float ee = av + adh;
        ee = ee > 0.f ? ee : SLOPE * ee;
        float ex = __expf(ee - mh);
        den += ex;
        // 8 bf16 channels = 16B per lane, 512B per warp per edge
        uint4 hv = *(const uint4*)&g_hb[(long long)s * HC + cbase];
        const __nv_bfloat162* hb = (const __nv_bfloat162*)&hv;
        float2 f0 = __bfloat1622float2(hb[0]);
        float2 f1 = __bfloat1622float2(hb[1]);
        float2 f2 = __bfloat1622float2(hb[2]);
        float2 f3 = __bfloat1622float2(hb[3]);
        acc[0] += ex * f0.x; acc[1] += ex * f0.y;
        acc[2] += ex * f1.x; acc[3] += ex * f1.y;
        acc[4] += ex * f2.x; acc[5] += ex * f2.y;
        acc[6] += ex * f3.x; acc[7] += ex * f3.y;
    }
    float inv = 1.f / (den + 1e-16f);
    float4 b0 = *(const float4*)&bias[cbase];
    float4 b1 = *(const float4*)&bias[cbase + 4];
    float4 o0, o1;
    o0.x = fmaxf(acc[0] * inv + b0.x, 0.f);
    o0.y = fmaxf(acc[1] * inv + b0.y, 0.f);
    o0.z = fmaxf(acc[2] * inv + b0.z, 0.f);
    o0.w = fmaxf(acc[3] * inv + b0.w, 0.f);
    o1.x = fmaxf(acc[4] * inv + b1.x, 0.f);
    o1.y = fmaxf(acc[5] * inv + b1.y, 0.f);
    o1.z = fmaxf(acc[6] * inv + b1.z, 0.f);
    o1.w = fmaxf(acc[7] * inv + b1.w, 0.f);
    *(float4*)&out[(long long)n * HC + cbase]     = o0;
    *(float4*)&out[(long long)n * HC + cbase + 4] = o1;
}

// ---------------- launcher -------------------------------------------------
extern "C" void kernel_launch(void* const* d_in, const int* in_sizes, int n_in,
                              void* d_out, int out_size) {
    const float* x  = (const float*)d_in[0];
    const int*   ei = (const int*)d_in[1];
    int E = in_sizes[1] / 2;
    const int* src = ei;
    const int* dst = ei + E;

    const float* W[3]  = {(const float*)d_in[2], (const float*)d_in[6],  (const float*)d_in[10]};
    const float* AS[3] = {(const float*)d_in[3], (const float*)d_in[7],  (const float*)d_in[11]};
    const float* AD[3] = {(const float*)d_in[4], (const float*)d_in[8],  (const float*)d_in[12]};
    const float* BI[3] = {(const float*)d_in[5], (const float*)d_in[9],  (const float*)d_in[13]};
    float* out = (float*)d_out;

    float* gx = nullptr;
    float* gh = nullptr;
    cudaGetSymbolAddress((void**)&gx, g_x);
    cudaGetSymbolAddress((void**)&gh, g_h);

    cudaFuncSetAttribute(gemm_tf32_kernel,
                         cudaFuncAttributeMaxDynamicSharedMemorySize,
                         GEMM_SMEM_BYTES);

    // CSR build (edge_index is identical for all layers)
    zero_off_kernel<<<(NN + 255) / 256, 256>>>();
    count_kernel<<<(E + 255) / 256, 256>>>(dst, E);
    scan_kernel<<<1, 1024>>>();
    scatter_kernel<<<(E + 255) / 256, 256>>>(src, dst, E);

    int ggrid = (NN + BM - 1) / BM;
    int attn_blocks = (NN * NHEADS * 32 + 255) / 256;
    int agg_blocks  = (NN + 7) / 8;

    // layer 0 (K = 128)
    gemm_tf32_kernel<<<ggrid, 256, GEMM_SMEM_BYTES>>>(x, W[0], gh, NN, F0);
    attn_kernel<<<attn_blocks, 256>>>(AS[0], AD[0]);
    agg_kernel<<<agg_blocks, 256>>>(BI[0], gx);

    // layer 1 (K = 256)
    gemm_tf32_kernel<<<ggrid, 256, GEMM_SMEM_BYTES>>>(gx, W[1], gh, NN, HC);
    attn_kernel<<<attn_blocks, 256>>>(AS[1], AD[1]);
    agg_kernel<<<agg_blocks, 256>>>(BI[1], gx);

    // layer 2 (K = 256), write final output
    gemm_tf32_kernel<<<ggrid, 256, GEMM_SMEM_BYTES>>>(gx, W[2], gh, NN, HC);
    attn_kernel<<<attn_blocks, 256>>>(AS[2], AD[2]);
    agg_kernel<<<agg_blocks, 256>>>(BI[2], out);
}